// round 12
// baseline (speedup 1.0000x reference)
#include <cuda_runtime.h>
#include <cstdint>

#define B_ 2
#define D_ 96
#define H_ 96
#define W_ 96
#define L_ (H_*W_)        // 9216
#define K_ 4
#define N_ 16
#define R_ 6
#define CDIM (R_ + 2*N_)  // 38
#define SGN 96            // number of segments per chain
#define SGL 96            // steps per segment
#define SGL2 48           // packed t2 per segment

// Scratch (allocation-free: __device__ globals)
__device__ float g_dd[B_*K_*(L_/2)*D_*4];  // [bk][l/2][d][4]
__device__ float g_bc[B_*K_*(L_/2)*N_*4];  // [bk][l/2][n][4]
__device__ float g_y [B_*K_*L_*D_];
__device__ float g_xT[B_*D_*L_];
__device__ float g_hend  [B_*K_*SGN*D_*N_];   // 4.7MB
__device__ float g_hstart[B_*K_*SGN*D_*N_];
__device__ float g_sd    [B_*K_*SGN*D_];

__device__ __forceinline__ float ex2f(float x){
    float y; asm("ex2.approx.ftz.f32 %0, %1;" : "=f"(y) : "f"(x)); return y;
}
__device__ __forceinline__ void cp16(void* dst_smem, const void* src){
    unsigned s = (unsigned)__cvta_generic_to_shared(dst_smem);
    asm volatile("cp.async.ca.shared.global [%0], [%1], 16;\n" :: "r"(s), "l"(src));
}
__device__ __forceinline__ void cp_commit(){ asm volatile("cp.async.commit_group;\n"); }
template<int n> __device__ __forceinline__ void cp_wait(){
    asm volatile("cp.async.wait_group %0;\n" :: "n"(n));
}
__device__ __forceinline__ void ffma2(unsigned long long& d, unsigned long long a,
                                      unsigned long long b, unsigned long long c){
    asm("fma.rn.f32x2 %0, %1, %2, %3;" : "=l"(d) : "l"(a), "l"(b), "l"(c));
}
__device__ __forceinline__ unsigned long long dup2(float w){
    unsigned long long r; asm("mov.b64 %0, {%1, %1};" : "=l"(r) : "f"(w)); return r;
}
__device__ __forceinline__ float2 unp2(unsigned long long v){
    float2 r; asm("mov.b64 {%0, %1}, %2;" : "=f"(r.x), "=f"(r.y) : "l"(v)); return r;
}

// ---------------------------------------------------------------------------
// Kernel 0: transpose x (h,w) per (b,d)
// ---------------------------------------------------------------------------
__global__ __launch_bounds__(256) void transpose_kernel(const float* __restrict__ x)
{
    __shared__ float t[32][33];
    int bd = blockIdx.x;
    int th = blockIdx.y / 3, tw = blockIdx.y % 3;
    int tx = threadIdx.x, ty = threadIdx.y;
    const float* src = x + (size_t)bd*L_;
    float* dst = g_xT + (size_t)bd*L_;
    int h0 = th*32, w0 = tw*32;
    #pragma unroll
    for (int i = 0; i < 4; i++)
        t[ty + i*8][tx] = src[(h0 + ty + i*8)*W_ + w0 + tx];
    __syncthreads();
    #pragma unroll
    for (int i = 0; i < 4; i++)
        dst[(w0 + ty + i*8)*H_ + h0 + tx] = t[tx][ty + i*8];
}

// ---------------------------------------------------------------------------
// Kernel 1: projection (unchanged)
// ---------------------------------------------------------------------------
#define WSQ_F  (CDIM*100)
#define XT_F   (D_*36)
#define CB_F   (CDIM*33)
__global__ __launch_bounds__(256) void proj_kernel(
    const float* __restrict__ x, const float* __restrict__ xpw,
    const float* __restrict__ dtw, const float* __restrict__ dtb)
{
    extern __shared__ float sm[];
    float* wsq  = sm;
    float* wdT  = wsq + WSQ_F;
    float* sbias= wdT + R_*D_;
    float* xt0  = sbias + D_;
    float* cb0  = xt0 + 2*XT_F;

    int bk = blockIdx.x; int b = bk>>2; int k = bk&3;
    int tid = threadIdx.x;
    int half = tid>>7, htid = tid&127;
    float* xt = xt0 + half*XT_F;
    float* cbuf = cb0 + half*CB_F;
    int l0 = blockIdx.y*64 + half*32;

    for (int i = tid; i < CDIM*D_; i += 256){
        int c = i/D_, d = i - c*D_;
        wsq[c*100+d] = xpw[k*CDIM*D_ + i];
    }
    for (int i = tid; i < D_*R_; i += 256){
        int d = i/R_, r = i - d*R_;
        wdT[r*D_+d] = dtw[k*D_*R_ + i];
    }
    if (tid < D_) sbias[tid] = dtb[k*D_+tid];

    const float* xsrc = ((k&1)==0) ? (x + (size_t)b*D_*L_)
                                   : (g_xT + (size_t)b*D_*L_);
    for (int i = htid; i < D_*32; i += 128){
        int d = i>>5, l = i&31;
        int ll = l0 + l;
        int pos = (k<2) ? ll : (L_-1-ll);
        xt[d*36 + l] = xsrc[(size_t)d*L_ + pos];
    }
    __syncthreads();

    int ci = htid & 15, lj = htid >> 4;
    {
        unsigned long long A0[2]={0ull,0ull}, A1[2]={0ull,0ull}, A2[2]={0ull,0ull};
        #pragma unroll 3
        for (int d4 = 0; d4 < D_/4; d4++){
            float4 w0 = *(const float4*)&wsq[ci*100 + d4*4];
            float4 w1 = *(const float4*)&wsq[(ci+16)*100 + d4*4];
            float4 w2 = (ci<6) ? *(const float4*)&wsq[(ci+32)*100 + d4*4]
                               : make_float4(0.f,0.f,0.f,0.f);
            const float* wq0 = &w0.x; const float* wq1 = &w1.x; const float* wq2 = &w2.x;
            #pragma unroll
            for (int j = 0; j < 4; j++){
                ulonglong2 xp = *(const ulonglong2*)&xt[(d4*4+j)*36 + lj*4];
                unsigned long long b0 = dup2(wq0[j]);
                unsigned long long b1 = dup2(wq1[j]);
                unsigned long long b2 = dup2(wq2[j]);
                ffma2(A0[0], b0, xp.x, A0[0]); ffma2(A0[1], b0, xp.y, A0[1]);
                ffma2(A1[0], b1, xp.x, A1[0]); ffma2(A1[1], b1, xp.y, A1[1]);
                ffma2(A2[0], b2, xp.x, A2[0]); ffma2(A2[1], b2, xp.y, A2[1]);
            }
        }
        #pragma unroll
        for (int q=0;q<2;q++){
            float2 v0 = unp2(A0[q]), v1 = unp2(A1[q]), v2 = unp2(A2[q]);
            int l = lj*4 + q*2;
            cbuf[ci*33 + l]        = v0.x;  cbuf[ci*33 + l + 1]        = v0.y;
            cbuf[(ci+16)*33 + l]   = v1.x;  cbuf[(ci+16)*33 + l + 1]   = v1.y;
            if (ci<6){
                cbuf[(ci+32)*33 + l] = v2.x; cbuf[(ci+32)*33 + l + 1] = v2.y;
            }
        }
    }
    __syncthreads();

    #pragma unroll 4
    for (int it = 0; it < 24; it++){
        int i = it*128 + htid;
        int l = i/96, d = i - l*96;
        float s = sbias[d];
        #pragma unroll
        for (int r=0;r<R_;r++) s = fmaf(cbuf[r*33+l], wdT[r*D_+d], s);
        float dlt = (s > 15.f) ? s : __logf(1.f + __expf(s));
        float u = xt[d*36+l];
        int ll = l0 + l;
        float2 v; v.x = dlt; v.y = dlt*u;
        *(float2*)&g_dd[(((size_t)bk*(L_/2) + (ll>>1))*D_ + d)*4 + (ll&1)*2] = v;
    }
    #pragma unroll
    for (int it = 0; it < 4; it++){
        int i = it*128 + htid;
        int l = i>>4, n = i&15;
        float2 v;
        v.x = cbuf[(R_+n)*33 + l];
        v.y = cbuf[(R_+N_+n)*33 + l];
        int ll = l0 + l;
        *(float2*)&g_bc[(((size_t)bk*(L_/2) + (ll>>1))*N_ + n)*4 + (ll&1)*2] = v;
    }
}

// ---------------------------------------------------------------------------
// Kernel 2A: fine-grained segment recurrence (h0=0): h_end0 + sum(delta).
// 9216 blocks x 128 thr; one-shot smem load (18.4KB) -> 12 blocks/SM.
// ---------------------------------------------------------------------------
__global__ __launch_bounds__(128) void scanA_kernel(const float* __restrict__ A_logs)
{
    __shared__ __align__(16) float sdd[SGL2*32];   // [t2][8][4]
    __shared__ __align__(16) float sbc[SGL2*64];   // [t2][16][4]

    int bx = blockIdx.x;
    int seg = bx % SGN; int cg = bx / SGN;     // cg = bk*12 + dblk
    int bk = cg / 12, dblk = cg % 12; int d0 = dblk*8;
    int k = bk & 3;
    int tid = threadIdx.x;
    int wid = tid>>5, lane = tid&31;
    int g = lane>>4, n = lane&15;
    int cidx = wid*2+g;
    int d = d0 + cidx;

    const float* gdd = g_dd + ((size_t)bk*(L_/2) + seg*SGL2)*D_*4;
    const float* gbc = g_bc + ((size_t)bk*(L_/2) + seg*SGL2)*N_*4;

    for (int i = tid; i < SGL2*8; i += 128){
        int l2 = i>>3, q = i&7;
        cp16(&sdd[l2*32 + q*4], gdd + ((size_t)l2*D_ + d0)*4 + q*4);
    }
    for (int i = tid; i < SGL2*16; i += 128){
        int l2 = i>>4, q = i&15;
        cp16(&sbc[l2*64 + q*4], gbc + (size_t)l2*N_*4 + q*4);
    }
    cp_commit();

    float Ah = -expf(A_logs[(k*D_+d)*N_ + n]) * 1.4426950408889634f;
    float h = 0.f, sd = 0.f;

    cp_wait<0>();
    __syncthreads();

    const float4* pdd = (const float4*)sdd + cidx;
    const float4* pbc = (const float4*)sbc + n;
    #pragma unroll 6
    for (int t2 = 0; t2 < SGL2; t2++){
        float4 dd = pdd[t2*8];
        float4 bc = pbc[t2*16];
        h = fmaf(ex2f(dd.x*Ah), h, dd.y*bc.x);
        h = fmaf(ex2f(dd.z*Ah), h, dd.w*bc.z);
        sd += dd.x + dd.z;
    }

    int idx = ((bk*SGN+seg)*D_ + d)*N_ + n;
    g_hend[idx] = h;
    if (n == 0) g_sd[(bk*SGN+seg)*D_ + d] = sd;
}

// ---------------------------------------------------------------------------
// Kernel 2B: serial 96-segment fixup per (bk,d,n), loads prefetched (MLP 2).
// ---------------------------------------------------------------------------
__global__ __launch_bounds__(256) void scanB_kernel(const float* __restrict__ A_logs)
{
    int i = blockIdx.x*256 + threadIdx.x;
    if (i >= B_*K_*D_*N_) return;
    int n = i & 15; int dn = i >> 4; int d = dn % D_; int bk = dn / D_;
    int k = bk & 3;
    float Ah = -expf(A_logs[(k*D_+d)*N_ + n]) * 1.4426950408889634f;
    float h = 0.f;
    int base = bk*SGN;
    float he = g_hend[((size_t)base*D_ + d)*N_ + n];
    float sd = g_sd[base*D_ + d];
    for (int s = 0; s < SGN; s++){
        float he_n = 0.f, sd_n = 0.f;
        if (s+1 < SGN){
            he_n = g_hend[((size_t)(base+s+1)*D_ + d)*N_ + n];
            sd_n = g_sd[(base+s+1)*D_ + d];
        }
        g_hstart[((size_t)(base+s)*D_ + d)*N_ + n] = h;
        h = fmaf(ex2f(Ah*sd), h, he);
        he = he_n; sd = sd_n;
    }
}

// ---------------------------------------------------------------------------
// Kernel 2C: fine-grained segment scan with known h_start, producing y.
// 9216 blocks; in-loop 2-level shfl reduce (latency covered by ~7 blocks/SM),
// 4 partials/chain to smem, bulk reduce at end.
// ---------------------------------------------------------------------------
#define SPROW 68     // per-t2 partial row: 8 chains x 4 classes x 2 steps + pad
__global__ __launch_bounds__(128) void scanC_kernel(const float* __restrict__ A_logs)
{
    __shared__ __align__(16) float sdd[SGL2*32];
    __shared__ __align__(16) float sbc[SGL2*64];
    __shared__ __align__(16) float sp [SGL2*SPROW];   // 13KB

    int bx = blockIdx.x;
    int seg = bx % SGN; int cg = bx / SGN;
    int bk = cg / 12, dblk = cg % 12; int d0 = dblk*8;
    int k = bk & 3;
    int tid = threadIdx.x;
    int wid = tid>>5, lane = tid&31;
    int g = lane>>4, n = lane&15;
    int cidx = wid*2+g;
    int d = d0 + cidx;

    const float* gdd = g_dd + ((size_t)bk*(L_/2) + seg*SGL2)*D_*4;
    const float* gbc = g_bc + ((size_t)bk*(L_/2) + seg*SGL2)*N_*4;
    float* gy = g_y + (size_t)bk*L_*D_;

    for (int i = tid; i < SGL2*8; i += 128){
        int l2 = i>>3, q = i&7;
        cp16(&sdd[l2*32 + q*4], gdd + ((size_t)l2*D_ + d0)*4 + q*4);
    }
    for (int i = tid; i < SGL2*16; i += 128){
        int l2 = i>>4, q = i&15;
        cp16(&sbc[l2*64 + q*4], gbc + (size_t)l2*N_*4 + q*4);
    }
    cp_commit();

    float Ah = -expf(A_logs[(k*D_+d)*N_ + n]) * 1.4426950408889634f;
    float h = g_hstart[((size_t)(bk*SGN+seg)*D_ + d)*N_ + n];

    cp_wait<0>();
    __syncthreads();

    const float4* pdd = (const float4*)sdd + cidx;
    const float4* pbc = (const float4*)sbc + n;
    #pragma unroll 4
    for (int t2 = 0; t2 < SGL2; t2++){
        float4 dd = pdd[t2*8];
        float4 bc = pbc[t2*16];
        h = fmaf(ex2f(dd.x*Ah), h, dd.y*bc.x);
        float p0 = h * bc.y;
        h = fmaf(ex2f(dd.z*Ah), h, dd.w*bc.z);
        float p1 = h * bc.w;
        p0 += __shfl_xor_sync(0xffffffffu, p0, 8);
        p1 += __shfl_xor_sync(0xffffffffu, p1, 8);
        p0 += __shfl_xor_sync(0xffffffffu, p0, 4);
        p1 += __shfl_xor_sync(0xffffffffu, p1, 4);
        if (n < 4){
            float2 st; st.x = p0; st.y = p1;
            *(float2*)&sp[t2*SPROW + cidx*8 + n*2] = st;
        }
    }
    __syncthreads();

    // reduce 4 class-partials per (t2, chain); store y
    int lb = seg*SGL;
    for (int T = tid; T < SGL2*8; T += 128){
        int t2 = T>>3, c8 = T&7;
        float4 v = *(const float4*)&sp[t2*SPROW + c8*8];
        float4 w = *(const float4*)&sp[t2*SPROW + c8*8 + 4];
        float e = (v.x+v.z) + (w.x+w.z);
        float o = (v.y+v.w) + (w.y+w.w);
        int l = lb + t2*2;
        gy[(size_t)l*D_ + d0 + c8]     = e;
        gy[(size_t)(l+1)*D_ + d0 + c8] = o;
    }
}

// ---------------------------------------------------------------------------
// Kernel 3: cross-merge + Ds*x + LayerNorm(D). 256 threads.
// ---------------------------------------------------------------------------
__global__ __launch_bounds__(256) void merge_kernel(
    const float* __restrict__ x, const float* __restrict__ Ds,
    const float* __restrict__ nw, const float* __restrict__ nb,
    float* __restrict__ out)
{
    __shared__ float xt[D_*33];
    int tid = threadIdx.x;
    int pix0 = blockIdx.x*32;
    int b = pix0 / L_;
    int rem0 = pix0 - b*L_;

    const float* xb = x + (size_t)b*D_*L_;
    for (int i = tid; i < D_*32; i += 256){
        int dd = i>>5, p = i&31;
        xt[dd*33 + p] = xb[(size_t)dd*L_ + rem0 + p];
    }
    __syncthreads();

    int wid = tid>>5, lane = tid&31;
    for (int pp = wid; pp < 32; pp += 8){
        int rem = rem0 + pp;
        int hh = rem / W_;
        int ww = rem - hh*W_;
        int l_wh = ww*H_ + hh;

        const float* y0 = g_y + ((size_t)(b*4+0)*L_ + rem)*D_;
        const float* y1 = g_y + ((size_t)(b*4+1)*L_ + l_wh)*D_;
        const float* y2 = g_y + ((size_t)(b*4+2)*L_ + (L_-1-rem))*D_;
        const float* y3 = g_y + ((size_t)(b*4+3)*L_ + (L_-1-l_wh))*D_;

        float v[3]; float s = 0.f, ss = 0.f;
        #pragma unroll
        for (int j=0;j<3;j++){
            int dd = lane + 32*j;
            float dsum = Ds[dd] + Ds[D_+dd] + Ds[2*D_+dd] + Ds[3*D_+dd];
            float acc = y0[dd] + y1[dd] + y2[dd] + y3[dd] + xt[dd*33+pp] * dsum;
            v[j] = acc; s += acc; ss = fmaf(acc, acc, ss);
        }
        #pragma unroll
        for (int o=16;o>0;o>>=1){
            s  += __shfl_xor_sync(0xffffffffu, s,  o);
            ss += __shfl_xor_sync(0xffffffffu, ss, o);
        }
        float mu  = s * (1.f/D_);
        float var = ss * (1.f/D_) - mu*mu;
        float rstd = rsqrtf(var + 1e-5f);
        float* op = out + ((size_t)b*L_ + rem)*D_;
        #pragma unroll
        for (int j=0;j<3;j++){
            int dd = lane + 32*j;
            op[dd] = (v[j]-mu)*rstd*nw[dd] + nb[dd];
        }
    }
}

// ---------------------------------------------------------------------------
extern "C" void kernel_launch(void* const* d_in, const int* in_sizes, int n_in,
                              void* d_out, int out_size)
{
    const float* x      = (const float*)d_in[0];
    const float* xpw    = (const float*)d_in[1];
    const float* dtw    = (const float*)d_in[2];
    const float* dtb    = (const float*)d_in[3];
    const float* A_logs = (const float*)d_in[4];
    const float* Ds     = (const float*)d_in[5];
    const float* nw     = (const float*)d_in[6];
    const float* nb     = (const float*)d_in[7];
    float* out = (float*)d_out;

    const int proj_smem = (WSQ_F + R_*D_ + D_ + 2*XT_F + 2*CB_F) * sizeof(float);
    cudaFuncSetAttribute(proj_kernel,
                         cudaFuncAttributeMaxDynamicSharedMemorySize, proj_smem);

    transpose_kernel<<<dim3(B_*D_, 9), dim3(32,8)>>>(x);
    proj_kernel<<<dim3(B_*K_, L_/64), 256, proj_smem>>>(x, xpw, dtw, dtb);
    scanA_kernel<<<B_*K_*12*SGN, 128>>>(A_logs);
    scanB_kernel<<<(B_*K_*D_*N_+255)/256, 256>>>(A_logs);
    scanC_kernel<<<B_*K_*12*SGN, 128>>>(A_logs);
    merge_kernel<<<B_*L_/32, 256>>>(x, Ds, nw, nb, out);
}

// round 14
// speedup vs baseline: 1.0835x; 1.0835x over previous
#include <cuda_runtime.h>
#include <cstdint>

#define B_ 2
#define D_ 96
#define H_ 96
#define W_ 96
#define L_ (H_*W_)        // 9216
#define K_ 4
#define N_ 16
#define R_ 6
#define CDIM (R_ + 2*N_)  // 38
#define SGN 96            // segments per chain
#define SGL 96            // steps per segment
#define SGL2 48           // packed t2 per segment

// Scratch (allocation-free: __device__ globals)
__device__ float g_dd[B_*K_*(L_/2)*D_*4];  // [bk][l/2][d][4]
__device__ float g_bc[B_*K_*(L_/2)*N_*4];  // [bk][l/2][n][4]
__device__ float g_y [B_*K_*L_*D_];
__device__ float g_xT[B_*D_*L_];
__device__ float g_hend  [B_*K_*SGN*D_*N_];
__device__ float g_hstart[B_*K_*SGN*D_*N_];
__device__ float g_sd    [B_*K_*SGN*D_];

__device__ __forceinline__ float ex2f(float x){
    float y; asm("ex2.approx.ftz.f32 %0, %1;" : "=f"(y) : "f"(x)); return y;
}
__device__ __forceinline__ void cp16(void* dst_smem, const void* src){
    unsigned s = (unsigned)__cvta_generic_to_shared(dst_smem);
    asm volatile("cp.async.ca.shared.global [%0], [%1], 16;\n" :: "r"(s), "l"(src));
}
__device__ __forceinline__ void cp_commit(){ asm volatile("cp.async.commit_group;\n"); }
template<int n> __device__ __forceinline__ void cp_wait(){
    asm volatile("cp.async.wait_group %0;\n" :: "n"(n));
}
__device__ __forceinline__ void ffma2(unsigned long long& d, unsigned long long a,
                                      unsigned long long b, unsigned long long c){
    asm("fma.rn.f32x2 %0, %1, %2, %3;" : "=l"(d) : "l"(a), "l"(b), "l"(c));
}
__device__ __forceinline__ unsigned long long dup2(float w){
    unsigned long long r; asm("mov.b64 %0, {%1, %1};" : "=l"(r) : "f"(w)); return r;
}
__device__ __forceinline__ float2 unp2(unsigned long long v){
    float2 r; asm("mov.b64 {%0, %1}, %2;" : "=f"(r.x), "=f"(r.y) : "l"(v)); return r;
}

// ---------------------------------------------------------------------------
// Kernel 0: transpose x (h,w) per (b,d)
// ---------------------------------------------------------------------------
__global__ __launch_bounds__(256) void transpose_kernel(const float* __restrict__ x)
{
    __shared__ float t[32][33];
    int bd = blockIdx.x;
    int th = blockIdx.y / 3, tw = blockIdx.y % 3;
    int tx = threadIdx.x, ty = threadIdx.y;
    const float* src = x + (size_t)bd*L_;
    float* dst = g_xT + (size_t)bd*L_;
    int h0 = th*32, w0 = tw*32;
    #pragma unroll
    for (int i = 0; i < 4; i++)
        t[ty + i*8][tx] = src[(h0 + ty + i*8)*W_ + w0 + tx];
    __syncthreads();
    #pragma unroll
    for (int i = 0; i < 4; i++)
        dst[(w0 + ty + i*8)*H_ + h0 + tx] = t[tx][ty + i*8];
}

// ---------------------------------------------------------------------------
// Kernel 1: projection. Epilogue repacked: one STG.128 per (l-pair, d) record.
// ---------------------------------------------------------------------------
#define WSQ_F  (CDIM*100)
#define XT_F   (D_*36)
#define CB_F   (CDIM*33)
__global__ __launch_bounds__(256) void proj_kernel(
    const float* __restrict__ x, const float* __restrict__ xpw,
    const float* __restrict__ dtw, const float* __restrict__ dtb)
{
    extern __shared__ float sm[];
    float* wsq  = sm;
    float* wdT  = wsq + WSQ_F;
    float* sbias= wdT + R_*D_;
    float* xt0  = sbias + D_;
    float* cb0  = xt0 + 2*XT_F;

    int bk = blockIdx.x; int b = bk>>2; int k = bk&3;
    int tid = threadIdx.x;
    int half = tid>>7, htid = tid&127;
    float* xt = xt0 + half*XT_F;
    float* cbuf = cb0 + half*CB_F;
    int l0 = blockIdx.y*64 + half*32;

    for (int i = tid; i < CDIM*D_; i += 256){
        int c = i/D_, d = i - c*D_;
        wsq[c*100+d] = xpw[k*CDIM*D_ + i];
    }
    for (int i = tid; i < D_*R_; i += 256){
        int d = i/R_, r = i - d*R_;
        wdT[r*D_+d] = dtw[k*D_*R_ + i];
    }
    if (tid < D_) sbias[tid] = dtb[k*D_+tid];

    const float* xsrc = ((k&1)==0) ? (x + (size_t)b*D_*L_)
                                   : (g_xT + (size_t)b*D_*L_);
    for (int i = htid; i < D_*32; i += 128){
        int d = i>>5, l = i&31;
        int ll = l0 + l;
        int pos = (k<2) ? ll : (L_-1-ll);
        xt[d*36 + l] = xsrc[(size_t)d*L_ + pos];
    }
    __syncthreads();

    int ci = htid & 15, lj = htid >> 4;
    {
        unsigned long long A0[2]={0ull,0ull}, A1[2]={0ull,0ull}, A2[2]={0ull,0ull};
        #pragma unroll 3
        for (int d4 = 0; d4 < D_/4; d4++){
            float4 w0 = *(const float4*)&wsq[ci*100 + d4*4];
            float4 w1 = *(const float4*)&wsq[(ci+16)*100 + d4*4];
            float4 w2 = (ci<6) ? *(const float4*)&wsq[(ci+32)*100 + d4*4]
                               : make_float4(0.f,0.f,0.f,0.f);
            const float* wq0 = &w0.x; const float* wq1 = &w1.x; const float* wq2 = &w2.x;
            #pragma unroll
            for (int j = 0; j < 4; j++){
                ulonglong2 xp = *(const ulonglong2*)&xt[(d4*4+j)*36 + lj*4];
                unsigned long long b0 = dup2(wq0[j]);
                unsigned long long b1 = dup2(wq1[j]);
                unsigned long long b2 = dup2(wq2[j]);
                ffma2(A0[0], b0, xp.x, A0[0]); ffma2(A0[1], b0, xp.y, A0[1]);
                ffma2(A1[0], b1, xp.x, A1[0]); ffma2(A1[1], b1, xp.y, A1[1]);
                ffma2(A2[0], b2, xp.x, A2[0]); ffma2(A2[1], b2, xp.y, A2[1]);
            }
        }
        #pragma unroll
        for (int q=0;q<2;q++){
            float2 v0 = unp2(A0[q]), v1 = unp2(A1[q]), v2 = unp2(A2[q]);
            int l = lj*4 + q*2;
            cbuf[ci*33 + l]        = v0.x;  cbuf[ci*33 + l + 1]        = v0.y;
            cbuf[(ci+16)*33 + l]   = v1.x;  cbuf[(ci+16)*33 + l + 1]   = v1.y;
            if (ci<6){
                cbuf[(ci+32)*33 + l] = v2.x; cbuf[(ci+32)*33 + l + 1] = v2.y;
            }
        }
    }
    __syncthreads();

    // epilogue dd: thread = (l-pair, d); one coalesced STG.128 per record
    #pragma unroll 4
    for (int it = 0; it < 12; it++){
        int i = it*128 + htid;            // 0..1535 = 16 l2 x 96 d
        int l2 = i/96, d = i - l2*96;
        int lA = l2*2, lB = lA+1;
        float sA = sbias[d], sB = sA;
        #pragma unroll
        for (int r=0;r<R_;r++){
            float w = wdT[r*D_+d];
            sA = fmaf(cbuf[r*33+lA], w, sA);
            sB = fmaf(cbuf[r*33+lB], w, sB);
        }
        float dA = (sA > 15.f) ? sA : __logf(1.f + __expf(sA));
        float dB = (sB > 15.f) ? sB : __logf(1.f + __expf(sB));
        float uA = xt[d*36+lA], uB = xt[d*36+lB];
        int ll2 = (l0>>1) + l2;
        float4 v; v.x = dA; v.y = dA*uA; v.z = dB; v.w = dB*uB;
        *(float4*)&g_dd[(((size_t)bk*(L_/2) + ll2)*D_ + d)*4] = v;
    }
    // epilogue bc: thread = (l-pair, n); one coalesced STG.128 per record
    #pragma unroll
    for (int it = 0; it < 2; it++){
        int i = it*128 + htid;            // 0..255 = 16 l2 x 16 n
        int n = i & 15, l2 = i >> 4;
        int lA = l2*2, lB = lA+1;
        float4 v;
        v.x = cbuf[(R_+n)*33 + lA];
        v.y = cbuf[(R_+N_+n)*33 + lA];
        v.z = cbuf[(R_+n)*33 + lB];
        v.w = cbuf[(R_+N_+n)*33 + lB];
        int ll2 = (l0>>1) + l2;
        *(float4*)&g_bc[(((size_t)bk*(L_/2) + ll2)*N_ + n)*4] = v;
    }
}

// ---------------------------------------------------------------------------
// Kernel 2A: fine-grained segment recurrence (h0=0): h_end0 + sum(delta).
// ---------------------------------------------------------------------------
__global__ __launch_bounds__(128) void scanA_kernel(const float* __restrict__ A_logs)
{
    __shared__ __align__(16) float sdd[SGL2*32];
    __shared__ __align__(16) float sbc[SGL2*64];

    int bx = blockIdx.x;
    int seg = bx % SGN; int cg = bx / SGN;
    int bk = cg / 12, dblk = cg % 12; int d0 = dblk*8;
    int k = bk & 3;
    int tid = threadIdx.x;
    int wid = tid>>5, lane = tid&31;
    int g = lane>>4, n = lane&15;
    int cidx = wid*2+g;
    int d = d0 + cidx;

    const float* gdd = g_dd + ((size_t)bk*(L_/2) + seg*SGL2)*D_*4;
    const float* gbc = g_bc + ((size_t)bk*(L_/2) + seg*SGL2)*N_*4;

    for (int i = tid; i < SGL2*8; i += 128){
        int l2 = i>>3, q = i&7;
        cp16(&sdd[l2*32 + q*4], gdd + ((size_t)l2*D_ + d0)*4 + q*4);
    }
    for (int i = tid; i < SGL2*16; i += 128){
        int l2 = i>>4, q = i&15;
        cp16(&sbc[l2*64 + q*4], gbc + (size_t)l2*N_*4 + q*4);
    }
    cp_commit();

    float Ah = -expf(A_logs[(k*D_+d)*N_ + n]) * 1.4426950408889634f;
    float h = 0.f, sd = 0.f;

    cp_wait<0>();
    __syncthreads();

    const float4* pdd = (const float4*)sdd + cidx;
    const float4* pbc = (const float4*)sbc + n;
    #pragma unroll 6
    for (int t2 = 0; t2 < SGL2; t2++){
        float4 dd = pdd[t2*8];
        float4 bc = pbc[t2*16];
        h = fmaf(ex2f(dd.x*Ah), h, dd.y*bc.x);
        h = fmaf(ex2f(dd.z*Ah), h, dd.w*bc.z);
        sd += dd.x + dd.z;
    }

    int idx = ((bk*SGN+seg)*D_ + d)*N_ + n;
    g_hend[idx] = h;
    if (n == 0) g_sd[(bk*SGN+seg)*D_ + d] = sd;
}

// ---------------------------------------------------------------------------
// Kernel 2B: block-staged segment-combine scan. 96 blocks x 128 thr.
// Stage all 96 segments' h_end (49KB) + sd (3KB) in smem; each thread does
// its 96-step fixup from smem; h_start written as coalesced 512B STGs.
// ---------------------------------------------------------------------------
#define SB_F (SGN*128 + SGN*8)   // 13056 floats = 52.2KB
__global__ __launch_bounds__(128) void scanB_kernel(const float* __restrict__ A_logs)
{
    extern __shared__ float sb[];
    float* s_he = sb;              // [96][128]
    float* s_sd = sb + SGN*128;    // [96][8]

    int bx = blockIdx.x;
    int bk = bx / 12, dblk = bx % 12; int d0 = dblk*8;
    int k = bk & 3;
    int tid = threadIdx.x;

    const float* ghe = g_hend + (size_t)bk*SGN*D_*N_ + d0*N_;
    for (int i = tid; i < SGN*32; i += 128){
        int s = i>>5, q = i&31;
        cp16(&s_he[s*128 + q*4], ghe + (size_t)s*D_*N_ + q*4);
    }
    cp_commit();
    for (int i = tid; i < SGN*8; i += 128){
        int s = i>>3, c8 = i&7;
        s_sd[i] = g_sd[(bk*SGN+s)*D_ + d0 + c8];
    }

    int c8 = tid>>4, n = tid&15;
    int d = d0 + c8;
    float Ah = -expf(A_logs[(k*D_+d)*N_ + n]) * 1.4426950408889634f;
    float h = 0.f;
    float* ghs = g_hstart + (size_t)bk*SGN*D_*N_ + d0*N_ + tid;

    cp_wait<0>();
    __syncthreads();

    #pragma unroll 4
    for (int s = 0; s < SGN; s++){
        ghs[(size_t)s*D_*N_] = h;
        float P = ex2f(Ah * s_sd[s*8 + c8]);
        h = fmaf(P, h, s_he[s*128 + tid]);
    }
}

// ---------------------------------------------------------------------------
// Kernel 2C: fine-grained segment scan with known h_start, producing y.
// ---------------------------------------------------------------------------
#define SPROW 68
__global__ __launch_bounds__(128) void scanC_kernel(const float* __restrict__ A_logs)
{
    __shared__ __align__(16) float sdd[SGL2*32];
    __shared__ __align__(16) float sbc[SGL2*64];
    __shared__ __align__(16) float sp [SGL2*SPROW];

    int bx = blockIdx.x;
    int seg = bx % SGN; int cg = bx / SGN;
    int bk = cg / 12, dblk = cg % 12; int d0 = dblk*8;
    int k = bk & 3;
    int tid = threadIdx.x;
    int wid = tid>>5, lane = tid&31;
    int g = lane>>4, n = lane&15;
    int cidx = wid*2+g;
    int d = d0 + cidx;

    const float* gdd = g_dd + ((size_t)bk*(L_/2) + seg*SGL2)*D_*4;
    const float* gbc = g_bc + ((size_t)bk*(L_/2) + seg*SGL2)*N_*4;
    float* gy = g_y + (size_t)bk*L_*D_;

    for (int i = tid; i < SGL2*8; i += 128){
        int l2 = i>>3, q = i&7;
        cp16(&sdd[l2*32 + q*4], gdd + ((size_t)l2*D_ + d0)*4 + q*4);
    }
    for (int i = tid; i < SGL2*16; i += 128){
        int l2 = i>>4, q = i&15;
        cp16(&sbc[l2*64 + q*4], gbc + (size_t)l2*N_*4 + q*4);
    }
    cp_commit();

    float Ah = -expf(A_logs[(k*D_+d)*N_ + n]) * 1.4426950408889634f;
    float h = g_hstart[((size_t)(bk*SGN+seg)*D_ + d)*N_ + n];

    cp_wait<0>();
    __syncthreads();

    const float4* pdd = (const float4*)sdd + cidx;
    const float4* pbc = (const float4*)sbc + n;
    #pragma unroll 4
    for (int t2 = 0; t2 < SGL2; t2++){
        float4 dd = pdd[t2*8];
        float4 bc = pbc[t2*16];
        h = fmaf(ex2f(dd.x*Ah), h, dd.y*bc.x);
        float p0 = h * bc.y;
        h = fmaf(ex2f(dd.z*Ah), h, dd.w*bc.z);
        float p1 = h * bc.w;
        p0 += __shfl_xor_sync(0xffffffffu, p0, 8);
        p1 += __shfl_xor_sync(0xffffffffu, p1, 8);
        p0 += __shfl_xor_sync(0xffffffffu, p0, 4);
        p1 += __shfl_xor_sync(0xffffffffu, p1, 4);
        if (n < 4){
            float2 st; st.x = p0; st.y = p1;
            *(float2*)&sp[t2*SPROW + cidx*8 + n*2] = st;
        }
    }
    __syncthreads();

    int lb = seg*SGL;
    for (int T = tid; T < SGL2*8; T += 128){
        int t2 = T>>3, c8 = T&7;
        float4 v = *(const float4*)&sp[t2*SPROW + c8*8];
        float4 w = *(const float4*)&sp[t2*SPROW + c8*8 + 4];
        float e = (v.x+v.z) + (w.x+w.z);
        float o = (v.y+v.w) + (w.y+w.w);
        int l = lb + t2*2;
        gy[(size_t)l*D_ + d0 + c8]     = e;
        gy[(size_t)(l+1)*D_ + d0 + c8] = o;
    }
}

// ---------------------------------------------------------------------------
// Kernel 3: cross-merge + Ds*x + LayerNorm(D). 256 threads.
// ---------------------------------------------------------------------------
__global__ __launch_bounds__(256) void merge_kernel(
    const float* __restrict__ x, const float* __restrict__ Ds,
    const float* __restrict__ nw, const float* __restrict__ nb,
    float* __restrict__ out)
{
    __shared__ float xt[D_*33];
    int tid = threadIdx.x;
    int pix0 = blockIdx.x*32;
    int b = pix0 / L_;
    int rem0 = pix0 - b*L_;

    const float* xb = x + (size_t)b*D_*L_;
    for (int i = tid; i < D_*32; i += 256){
        int dd = i>>5, p = i&31;
        xt[dd*33 + p] = xb[(size_t)dd*L_ + rem0 + p];
    }
    __syncthreads();

    int wid = tid>>5, lane = tid&31;
    for (int pp = wid; pp < 32; pp += 8){
        int rem = rem0 + pp;
        int hh = rem / W_;
        int ww = rem - hh*W_;
        int l_wh = ww*H_ + hh;

        const float* y0 = g_y + ((size_t)(b*4+0)*L_ + rem)*D_;
        const float* y1 = g_y + ((size_t)(b*4+1)*L_ + l_wh)*D_;
        const float* y2 = g_y + ((size_t)(b*4+2)*L_ + (L_-1-rem))*D_;
        const float* y3 = g_y + ((size_t)(b*4+3)*L_ + (L_-1-l_wh))*D_;

        float v[3]; float s = 0.f, ss = 0.f;
        #pragma unroll
        for (int j=0;j<3;j++){
            int dd = lane + 32*j;
            float dsum = Ds[dd] + Ds[D_+dd] + Ds[2*D_+dd] + Ds[3*D_+dd];
            float acc = y0[dd] + y1[dd] + y2[dd] + y3[dd] + xt[dd*33+pp] * dsum;
            v[j] = acc; s += acc; ss = fmaf(acc, acc, ss);
        }
        #pragma unroll
        for (int o=16;o>0;o>>=1){
            s  += __shfl_xor_sync(0xffffffffu, s,  o);
            ss += __shfl_xor_sync(0xffffffffu, ss, o);
        }
        float mu  = s * (1.f/D_);
        float var = ss * (1.f/D_) - mu*mu;
        float rstd = rsqrtf(var + 1e-5f);
        float* op = out + ((size_t)b*L_ + rem)*D_;
        #pragma unroll
        for (int j=0;j<3;j++){
            int dd = lane + 32*j;
            op[dd] = (v[j]-mu)*rstd*nw[dd] + nb[dd];
        }
    }
}

// ---------------------------------------------------------------------------
extern "C" void kernel_launch(void* const* d_in, const int* in_sizes, int n_in,
                              void* d_out, int out_size)
{
    const float* x      = (const float*)d_in[0];
    const float* xpw    = (const float*)d_in[1];
    const float* dtw    = (const float*)d_in[2];
    const float* dtb    = (const float*)d_in[3];
    const float* A_logs = (const float*)d_in[4];
    const float* Ds     = (const float*)d_in[5];
    const float* nw     = (const float*)d_in[6];
    const float* nb     = (const float*)d_in[7];
    float* out = (float*)d_out;

    const int proj_smem = (WSQ_F + R_*D_ + D_ + 2*XT_F + 2*CB_F) * sizeof(float);
    cudaFuncSetAttribute(proj_kernel,
                         cudaFuncAttributeMaxDynamicSharedMemorySize, proj_smem);
    const int sb_smem = SB_F * sizeof(float);
    cudaFuncSetAttribute(scanB_kernel,
                         cudaFuncAttributeMaxDynamicSharedMemorySize, sb_smem);

    transpose_kernel<<<dim3(B_*D_, 9), dim3(32,8)>>>(x);
    proj_kernel<<<dim3(B_*K_, L_/64), 256, proj_smem>>>(x, xpw, dtw, dtb);
    scanA_kernel<<<B_*K_*12*SGN, 128>>>(A_logs);
    scanB_kernel<<<B_*K_*12, 128, sb_smem>>>(A_logs);
    scanC_kernel<<<B_*K_*12*SGN, 128>>>(A_logs);
    merge_kernel<<<B_*L_/32, 256>>>(x, Ds, nw, nb, out);
}